// round 6
// baseline (speedup 1.0000x reference)
#include <cuda_runtime.h>
#include <cuda_bf16.h>
#include <cstdint>
#include <cstddef>

// Problem constants (fixed by setup_inputs)
#define BB 2
#define SS 2048
#define DD 3584
#define HH 28
#define KVH 4
#define HDIM 128
#define NREP 7
#define MROWS (BB*SS)          // 4096
#define QN (HH*HDIM)           // 3584
#define KN (KVH*HDIM)          // 512
#define ATT_SCALE 0.08838834764831845f

// ---------------------------------------------------------------------------
// Scratch (device globals; allocation inside kernel_launch is forbidden).
// Referenced DIRECTLY from device code — no cudaGetSymbolAddress on host.
// ---------------------------------------------------------------------------
__device__ float g_q[(size_t)MROWS * QN];   // 4096 x 3584
__device__ float g_k[(size_t)MROWS * KN];   // 4096 x 512
__device__ float g_v[(size_t)MROWS * KN];   // 4096 x 512
__device__ float g_o[(size_t)MROWS * QN];   // 4096 x 3584  (attention output)

#define BUF_EXT 0
#define BUF_Q   1
#define BUF_K   2
#define BUF_V   3
#define BUF_O   4

__device__ __forceinline__ const float* src_buf(int sel, const float* ext) {
    switch (sel) {
        case BUF_Q: return g_q;
        case BUF_O: return g_o;
        default:    return ext;
    }
}
__device__ __forceinline__ float* dst_buf(int sel, float* ext) {
    switch (sel) {
        case BUF_Q: return g_q;
        case BUF_K: return g_k;
        case BUF_V: return g_v;
        case BUF_O: return g_o;
        default:    return ext;
    }
}

__device__ __forceinline__ uint32_t f2tf32(float x) {
    uint32_t r;
    asm("cvt.rna.tf32.f32 %0, %1;" : "=r"(r) : "f"(x));
    return r;
}

// ---------------------------------------------------------------------------
// NT GEMM on tf32 tensor cores: C[m,n] = sum_k A[m,k]*B[n,k] (+ bias[n]).
// 128x128 block tile, BK=16, double-buffered smem, 256 threads = 8 warps.
// Warp grid 2x4: each warp owns 64x32 = 4x4 fragments of m16n8k8.
// Smem rows padded to 20 words: fragment LDS addr = 20*r + c -> (4r+t) mod 32
// distinct across the 8x4 lane grid => conflict-free.
// Requires: M%128==0, N%128==0, K%16==0 (all uses: K=3584).
// ---------------------------------------------------------------------------
__global__ __launch_bounds__(256) void gemm_tf32(
    const float* __restrict__ Aext, int a_sel,
    const float* __restrict__ B,
    const float* __restrict__ bias,
    float* __restrict__ Cext, int c_sel,
    int M, int N, int K)
{
    const float* A = src_buf(a_sel, Aext);
    float* C = dst_buf(c_sel, Cext);

    __shared__ uint32_t As[2][128][20];
    __shared__ uint32_t Bs[2][128][20];

    const int bm = blockIdx.y * 128;
    const int bn = blockIdx.x * 128;
    const int tid = threadIdx.x;
    const int warp = tid >> 5;
    const int lane = tid & 31;
    const int g = lane >> 2;        // groupID (row within fragment)
    const int t = lane & 3;         // thread-in-group (col within fragment)
    const int wm = (warp >> 2) * 64;  // warp m offset in tile
    const int wn = (warp & 3) * 32;   // warp n offset in tile

    // Global-load assignment: each thread loads 2 float4 (8 floats) of A and B
    const int lrow = tid >> 1;            // 0..127
    const int lcol = (tid & 1) * 8;       // 0 or 8
    const float* aRow = A + (size_t)(bm + lrow) * K + lcol;
    const float* bRow = B + (size_t)(bn + lrow) * K + lcol;

    float acc[4][4][4];
#pragma unroll
    for (int mi = 0; mi < 4; mi++)
#pragma unroll
        for (int ni = 0; ni < 4; ni++)
#pragma unroll
            for (int e = 0; e < 4; e++) acc[mi][ni][e] = 0.f;

    const int kIters = K >> 4;

    // Prologue: load tile 0
    {
        float4 a0 = *(const float4*)(aRow);
        float4 a1 = *(const float4*)(aRow + 4);
        float4 b0 = *(const float4*)(bRow);
        float4 b1 = *(const float4*)(bRow + 4);
        As[0][lrow][lcol + 0] = f2tf32(a0.x); As[0][lrow][lcol + 1] = f2tf32(a0.y);
        As[0][lrow][lcol + 2] = f2tf32(a0.z); As[0][lrow][lcol + 3] = f2tf32(a0.w);
        As[0][lrow][lcol + 4] = f2tf32(a1.x); As[0][lrow][lcol + 5] = f2tf32(a1.y);
        As[0][lrow][lcol + 6] = f2tf32(a1.z); As[0][lrow][lcol + 7] = f2tf32(a1.w);
        Bs[0][lrow][lcol + 0] = f2tf32(b0.x); Bs[0][lrow][lcol + 1] = f2tf32(b0.y);
        Bs[0][lrow][lcol + 2] = f2tf32(b0.z); Bs[0][lrow][lcol + 3] = f2tf32(b0.w);
        Bs[0][lrow][lcol + 4] = f2tf32(b1.x); Bs[0][lrow][lcol + 5] = f2tf32(b1.y);
        Bs[0][lrow][lcol + 6] = f2tf32(b1.z); Bs[0][lrow][lcol + 7] = f2tf32(b1.w);
    }
    __syncthreads();

    int buf = 0;
#pragma unroll 1
    for (int it = 0; it < kIters; it++) {
        const bool hasNext = (it + 1) < kIters;
        float4 a0, a1, b0, b1;
        if (hasNext) {
            const int k0 = (it + 1) << 4;
            a0 = *(const float4*)(aRow + k0);
            a1 = *(const float4*)(aRow + k0 + 4);
            b0 = *(const float4*)(bRow + k0);
            b1 = *(const float4*)(bRow + k0 + 4);
        }

        // Compute on current buffer: 2 k-steps of 8
#pragma unroll
        for (int ks = 0; ks < 16; ks += 8) {
            uint32_t af[4][4];
#pragma unroll
            for (int mi = 0; mi < 4; mi++) {
                const int r = wm + mi * 16;
                af[mi][0] = As[buf][r + g][ks + t];
                af[mi][1] = As[buf][r + g + 8][ks + t];
                af[mi][2] = As[buf][r + g][ks + t + 4];
                af[mi][3] = As[buf][r + g + 8][ks + t + 4];
            }
            uint32_t bfr[4][2];
#pragma unroll
            for (int ni = 0; ni < 4; ni++) {
                const int c = wn + ni * 8;
                bfr[ni][0] = Bs[buf][c + g][ks + t];
                bfr[ni][1] = Bs[buf][c + g][ks + t + 4];
            }
#pragma unroll
            for (int mi = 0; mi < 4; mi++)
#pragma unroll
                for (int ni = 0; ni < 4; ni++) {
                    asm volatile(
                        "mma.sync.aligned.m16n8k8.row.col.f32.tf32.tf32.f32 "
                        "{%0,%1,%2,%3}, {%4,%5,%6,%7}, {%8,%9}, {%0,%1,%2,%3};\n"
                        : "+f"(acc[mi][ni][0]), "+f"(acc[mi][ni][1]),
                          "+f"(acc[mi][ni][2]), "+f"(acc[mi][ni][3])
                        : "r"(af[mi][0]), "r"(af[mi][1]), "r"(af[mi][2]), "r"(af[mi][3]),
                          "r"(bfr[ni][0]), "r"(bfr[ni][1]));
                }
        }

        if (hasNext) {
            const int nb = buf ^ 1;
            As[nb][lrow][lcol + 0] = f2tf32(a0.x); As[nb][lrow][lcol + 1] = f2tf32(a0.y);
            As[nb][lrow][lcol + 2] = f2tf32(a0.z); As[nb][lrow][lcol + 3] = f2tf32(a0.w);
            As[nb][lrow][lcol + 4] = f2tf32(a1.x); As[nb][lrow][lcol + 5] = f2tf32(a1.y);
            As[nb][lrow][lcol + 6] = f2tf32(a1.z); As[nb][lrow][lcol + 7] = f2tf32(a1.w);
            Bs[nb][lrow][lcol + 0] = f2tf32(b0.x); Bs[nb][lrow][lcol + 1] = f2tf32(b0.y);
            Bs[nb][lrow][lcol + 2] = f2tf32(b0.z); Bs[nb][lrow][lcol + 3] = f2tf32(b0.w);
            Bs[nb][lrow][lcol + 4] = f2tf32(b1.x); Bs[nb][lrow][lcol + 5] = f2tf32(b1.y);
            Bs[nb][lrow][lcol + 6] = f2tf32(b1.z); Bs[nb][lrow][lcol + 7] = f2tf32(b1.w);
            __syncthreads();
            buf = nb;
        }
    }

    // Epilogue: acc[mi][ni] -> C rows (g, g+8), cols (2t, 2t+1), plus bias
#pragma unroll
    for (int ni = 0; ni < 4; ni++) {
        const int cc = bn + wn + ni * 8 + 2 * t;
        float2 bv = make_float2(0.f, 0.f);
        if (bias) bv = *(const float2*)(bias + cc);
#pragma unroll
        for (int mi = 0; mi < 4; mi++) {
            const int rr = bm + wm + mi * 16 + g;
            float2 c0, c1;
            c0.x = acc[mi][ni][0] + bv.x; c0.y = acc[mi][ni][1] + bv.y;
            c1.x = acc[mi][ni][2] + bv.x; c1.y = acc[mi][ni][3] + bv.y;
            *(float2*)(C + (size_t)rr * N + cc) = c0;
            *(float2*)(C + (size_t)(rr + 8) * N + cc) = c1;
        }
    }
}

// ---------------------------------------------------------------------------
// RoPE: interleaved pairs (2d, 2d+1) per head, position = row % S (start_pos=0)
// ---------------------------------------------------------------------------
__global__ void rope_kernel(const float* __restrict__ fc, const float* __restrict__ fs)
{
    const int NQ = MROWS * HH * 64;
    int idx = blockIdx.x * 256 + threadIdx.x;
    if (idx < NQ) {
        int d = idx & 63;
        int h = (idx >> 6) % HH;
        int row = idx / (64 * HH);
        int s = row & (SS - 1);
        float c = fc[s * 64 + d], sn = fs[s * 64 + d];
        float* p = g_q + (size_t)row * QN + h * HDIM + 2 * d;
        float xr = p[0], xi = p[1];
        p[0] = xr * c - xi * sn;
        p[1] = xr * sn + xi * c;
    } else {
        int j = idx - NQ;
        int d = j & 63;
        int h = (j >> 6) & 3;
        int row = j >> 8;
        int s = row & (SS - 1);
        float c = fc[s * 64 + d], sn = fs[s * 64 + d];
        float* p = g_k + (size_t)row * KN + h * HDIM + 2 * d;
        float xr = p[0], xi = p[1];
        p[0] = xr * c - xi * sn;
        p[1] = xr * sn + xi * c;
    }
}

// ---------------------------------------------------------------------------
// Flash attention (fp32 SIMT), unchanged from the passing R3 kernel.
// ---------------------------------------------------------------------------
__global__ __launch_bounds__(256) void flash_kernel()
{
    extern __shared__ float sm[];
    float* Qt = sm;                 // 128*68
    float* Kt = sm + 8704;          // 128*68
    float* Vs = sm + 17408;         // 64*132
    float* Ps = sm + 25856;         // 64*68

    const int m0 = (gridDim.x - 1 - blockIdx.x) * 64;   // heavy blocks first
    const int h = blockIdx.y;
    const int b = blockIdx.z;
    const int kvh = h / NREP;
    const int tid = threadIdx.x;
    const int tx = tid & 15;
    const int ty = tid >> 4;

    const float* qb = g_q + (size_t)(b * SS + m0) * QN + h * HDIM;
#pragma unroll
    for (int it = 0; it < 8; it++) {
        int e = it * 256 + tid;
        int r = e >> 5;
        int d4 = (e & 31) << 2;
        float4 val = *(const float4*)(qb + (size_t)r * QN + d4);
        Qt[(d4 + 0) * 68 + r] = val.x * ATT_SCALE;
        Qt[(d4 + 1) * 68 + r] = val.y * ATT_SCALE;
        Qt[(d4 + 2) * 68 + r] = val.z * ATT_SCALE;
        Qt[(d4 + 3) * 68 + r] = val.w * ATT_SCALE;
    }

    float mrow[4], lrow[4];
#pragma unroll
    for (int i = 0; i < 4; i++) { mrow[i] = -1e30f; lrow[i] = 0.f; }
    float accO[4][8];
#pragma unroll
    for (int i = 0; i < 4; i++)
#pragma unroll
        for (int j = 0; j < 8; j++) accO[i][j] = 0.f;

    const int jcount = m0 / 64 + 1;  // causal
    for (int jt = 0; jt < jcount; jt++) {
        const int t0 = jt * 64;
        __syncthreads();

        const float* kb = g_k + (size_t)(b * SS + t0) * KN + kvh * HDIM;
        const float* vb = g_v + (size_t)(b * SS + t0) * KN + kvh * HDIM;
#pragma unroll
        for (int it = 0; it < 8; it++) {
            int e = it * 256 + tid;
            int r = e >> 5;
            int d4 = (e & 31) << 2;
            float4 val = *(const float4*)(kb + (size_t)r * KN + d4);
            Kt[(d4 + 0) * 68 + r] = val.x;
            Kt[(d4 + 1) * 68 + r] = val.y;
            Kt[(d4 + 2) * 68 + r] = val.z;
            Kt[(d4 + 3) * 68 + r] = val.w;
            float4 vv = *(const float4*)(vb + (size_t)r * KN + d4);
            *(float4*)&Vs[r * 132 + d4] = vv;
        }
        __syncthreads();

        float sc[4][4];
#pragma unroll
        for (int i = 0; i < 4; i++)
#pragma unroll
            for (int j = 0; j < 4; j++) sc[i][j] = 0.f;
#pragma unroll 8
        for (int kk = 0; kk < 128; kk++) {
            float4 a = *(const float4*)&Qt[kk * 68 + ty * 4];
            float4 bv = *(const float4*)&Kt[kk * 68 + tx * 4];
            float av[4] = {a.x, a.y, a.z, a.w};
            float bb2[4] = {bv.x, bv.y, bv.z, bv.w};
#pragma unroll
            for (int i = 0; i < 4; i++)
#pragma unroll
                for (int j = 0; j < 4; j++)
                    sc[i][j] = fmaf(av[i], bb2[j], sc[i][j]);
        }

        if (t0 == m0) {
#pragma unroll
            for (int i = 0; i < 4; i++)
#pragma unroll
                for (int j = 0; j < 4; j++)
                    if (t0 + tx * 4 + j > m0 + ty * 4 + i) sc[i][j] = -1e30f;
        }

        float alpha[4];
#pragma unroll
        for (int i = 0; i < 4; i++) {
            float rm = fmaxf(fmaxf(sc[i][0], sc[i][1]), fmaxf(sc[i][2], sc[i][3]));
            rm = fmaxf(rm, __shfl_xor_sync(0xffffffffu, rm, 1));
            rm = fmaxf(rm, __shfl_xor_sync(0xffffffffu, rm, 2));
            rm = fmaxf(rm, __shfl_xor_sync(0xffffffffu, rm, 4));
            rm = fmaxf(rm, __shfl_xor_sync(0xffffffffu, rm, 8));
            float mn = fmaxf(mrow[i], rm);
            alpha[i] = __expf(mrow[i] - mn);
            float rs = 0.f;
#pragma unroll
            for (int j = 0; j < 4; j++) {
                sc[i][j] = __expf(sc[i][j] - mn);
                rs += sc[i][j];
            }
            rs += __shfl_xor_sync(0xffffffffu, rs, 1);
            rs += __shfl_xor_sync(0xffffffffu, rs, 2);
            rs += __shfl_xor_sync(0xffffffffu, rs, 4);
            rs += __shfl_xor_sync(0xffffffffu, rs, 8);
            lrow[i] = lrow[i] * alpha[i] + rs;
            mrow[i] = mn;
        }
#pragma unroll
        for (int i = 0; i < 4; i++)
#pragma unroll
            for (int j = 0; j < 8; j++) accO[i][j] *= alpha[i];

#pragma unroll
        for (int i = 0; i < 4; i++)
#pragma unroll
            for (int j = 0; j < 4; j++)
                Ps[(tx * 4 + j) * 68 + ty * 4 + i] = sc[i][j];
        __syncthreads();

#pragma unroll 4
        for (int t = 0; t < 64; t++) {
            float4 p = *(const float4*)&Ps[t * 68 + ty * 4];
            float4 v0 = *(const float4*)&Vs[t * 132 + tx * 8];
            float4 v1 = *(const float4*)&Vs[t * 132 + tx * 8 + 4];
            float pv[4] = {p.x, p.y, p.z, p.w};
            float vv[8] = {v0.x, v0.y, v0.z, v0.w, v1.x, v1.y, v1.z, v1.w};
#pragma unroll
            for (int i = 0; i < 4; i++)
#pragma unroll
                for (int j = 0; j < 8; j++)
                    accO[i][j] = fmaf(pv[i], vv[j], accO[i][j]);
        }
    }

#pragma unroll
    for (int i = 0; i < 4; i++) {
        float inv = 1.f / lrow[i];
        float* ob = g_o + (size_t)(b * SS + m0 + ty * 4 + i) * QN + h * HDIM + tx * 8;
        float4 r0, r1;
        r0.x = accO[i][0] * inv; r0.y = accO[i][1] * inv;
        r0.z = accO[i][2] * inv; r0.w = accO[i][3] * inv;
        r1.x = accO[i][4] * inv; r1.y = accO[i][5] * inv;
        r1.z = accO[i][6] * inv; r1.w = accO[i][7] * inv;
        *(float4*)(ob) = r0;
        *(float4*)(ob + 4) = r1;
    }
}

// ---------------------------------------------------------------------------
// kernel_launch
// ---------------------------------------------------------------------------
extern "C" void kernel_launch(void* const* d_in, const int* in_sizes, int n_in,
                              void* d_out, int out_size)
{
    const float* x    = (const float*)d_in[0];
    const float* wq_w = (const float*)d_in[1];
    const float* wq_b = (const float*)d_in[2];
    const float* wk_w = (const float*)d_in[3];
    const float* wk_b = (const float*)d_in[4];
    const float* wv_w = (const float*)d_in[5];
    const float* wv_b = (const float*)d_in[6];
    const float* wo_w = (const float*)d_in[7];
    const float* fc   = (const float*)d_in[10];
    const float* fs   = (const float*)d_in[11];
    float* out = (float*)d_out;

    const int flash_smem = 30208 * 4;  // 120,832 bytes
    cudaFuncSetAttribute(flash_kernel, cudaFuncAttributeMaxDynamicSharedMemorySize, flash_smem);

    // QKV projections on tf32 tensor cores
    gemm_tf32<<<dim3(QN / 128, MROWS / 128), 256>>>(x, BUF_EXT, wq_w, wq_b, nullptr, BUF_Q, MROWS, QN, DD);
    gemm_tf32<<<dim3(KN / 128, MROWS / 128), 256>>>(x, BUF_EXT, wk_w, wk_b, nullptr, BUF_K, MROWS, KN, DD);
    gemm_tf32<<<dim3(KN / 128, MROWS / 128), 256>>>(x, BUF_EXT, wv_w, wv_b, nullptr, BUF_V, MROWS, KN, DD);

    // RoPE on g_q and g_k
    rope_kernel<<<(MROWS * HH * 64 + MROWS * KVH * 64) / 256, 256>>>(fc, fs);

    // Causal GQA flash attention: g_q,g_k,g_v -> g_o
    flash_kernel<<<dim3(SS / 64, HH, BB), 256, flash_smem>>>();

    // Output projection: g_o @ wo_w^T -> out
    gemm_tf32<<<dim3(QN / 128, MROWS / 128), 256>>>(nullptr, BUF_O, wo_w, nullptr, out, BUF_EXT, MROWS, QN, DD);
}

// round 7
// speedup vs baseline: 1.6737x; 1.6737x over previous
#include <cuda_runtime.h>
#include <cuda_bf16.h>
#include <cstdint>
#include <cstddef>

// Problem constants (fixed by setup_inputs)
#define BB 2
#define SS 2048
#define DD 3584
#define HH 28
#define KVH 4
#define HDIM 128
#define NREP 7
#define MROWS (BB*SS)          // 4096
#define QN (HH*HDIM)           // 3584
#define KN (KVH*HDIM)          // 512
#define ATT_SCALE 0.08838834764831845f

// ---------------------------------------------------------------------------
// Scratch (device globals)
// ---------------------------------------------------------------------------
__device__ float g_q[(size_t)MROWS * QN];   // 4096 x 3584 (post-rope: scaled + tf32-rounded)
__device__ float g_k[(size_t)MROWS * KN];   // 4096 x 512  (post-rope: tf32-rounded)
__device__ float g_v[(size_t)MROWS * KN];   // 4096 x 512  (tf32-rounded)
__device__ float g_o[(size_t)MROWS * QN];   // 4096 x 3584 (attention output, fp32)

#define BUF_EXT 0
#define BUF_Q   1
#define BUF_K   2
#define BUF_V   3
#define BUF_O   4

__device__ __forceinline__ const float* src_buf(int sel, const float* ext) {
    switch (sel) {
        case BUF_Q: return g_q;
        case BUF_O: return g_o;
        default:    return ext;
    }
}
__device__ __forceinline__ float* dst_buf(int sel, float* ext) {
    switch (sel) {
        case BUF_Q: return g_q;
        case BUF_K: return g_k;
        case BUF_V: return g_v;
        case BUF_O: return g_o;
        default:    return ext;
    }
}

__device__ __forceinline__ uint32_t f2tf32(float x) {
    uint32_t r;
    asm("cvt.rna.tf32.f32 %0, %1;" : "=r"(r) : "f"(x));
    return r;
}
// tf32-round but keep as fp32 value (low mantissa bits zeroed)
__device__ __forceinline__ float tf32r(float x) {
    return __uint_as_float(f2tf32(x));
}

__device__ __forceinline__ void mma_tf32(float acc[4],
                                         uint32_t a0, uint32_t a1, uint32_t a2, uint32_t a3,
                                         uint32_t b0, uint32_t b1) {
    asm volatile(
        "mma.sync.aligned.m16n8k8.row.col.f32.tf32.tf32.f32 "
        "{%0,%1,%2,%3}, {%4,%5,%6,%7}, {%8,%9}, {%0,%1,%2,%3};\n"
        : "+f"(acc[0]), "+f"(acc[1]), "+f"(acc[2]), "+f"(acc[3])
        : "r"(a0), "r"(a1), "r"(a2), "r"(a3), "r"(b0), "r"(b1));
}

// ---------------------------------------------------------------------------
// NT GEMM on tf32 tensor cores (unchanged from passing R6 kernel)
// ---------------------------------------------------------------------------
__global__ __launch_bounds__(256) void gemm_tf32(
    const float* __restrict__ Aext, int a_sel,
    const float* __restrict__ B,
    const float* __restrict__ bias,
    float* __restrict__ Cext, int c_sel,
    int M, int N, int K)
{
    const float* A = src_buf(a_sel, Aext);
    float* C = dst_buf(c_sel, Cext);

    __shared__ uint32_t As[2][128][20];
    __shared__ uint32_t Bs[2][128][20];

    const int bm = blockIdx.y * 128;
    const int bn = blockIdx.x * 128;
    const int tid = threadIdx.x;
    const int warp = tid >> 5;
    const int lane = tid & 31;
    const int g = lane >> 2;
    const int t = lane & 3;
    const int wm = (warp >> 2) * 64;
    const int wn = (warp & 3) * 32;

    const int lrow = tid >> 1;
    const int lcol = (tid & 1) * 8;
    const float* aRow = A + (size_t)(bm + lrow) * K + lcol;
    const float* bRow = B + (size_t)(bn + lrow) * K + lcol;

    float acc[4][4][4];
#pragma unroll
    for (int mi = 0; mi < 4; mi++)
#pragma unroll
        for (int ni = 0; ni < 4; ni++)
#pragma unroll
            for (int e = 0; e < 4; e++) acc[mi][ni][e] = 0.f;

    const int kIters = K >> 4;

    {
        float4 a0 = *(const float4*)(aRow);
        float4 a1 = *(const float4*)(aRow + 4);
        float4 b0 = *(const float4*)(bRow);
        float4 b1 = *(const float4*)(bRow + 4);
        As[0][lrow][lcol + 0] = f2tf32(a0.x); As[0][lrow][lcol + 1] = f2tf32(a0.y);
        As[0][lrow][lcol + 2] = f2tf32(a0.z); As[0][lrow][lcol + 3] = f2tf32(a0.w);
        As[0][lrow][lcol + 4] = f2tf32(a1.x); As[0][lrow][lcol + 5] = f2tf32(a1.y);
        As[0][lrow][lcol + 6] = f2tf32(a1.z); As[0][lrow][lcol + 7] = f2tf32(a1.w);
        Bs[0][lrow][lcol + 0] = f2tf32(b0.x); Bs[0][lrow][lcol + 1] = f2tf32(b0.y);
        Bs[0][lrow][lcol + 2] = f2tf32(b0.z); Bs[0][lrow][lcol + 3] = f2tf32(b0.w);
        Bs[0][lrow][lcol + 4] = f2tf32(b1.x); Bs[0][lrow][lcol + 5] = f2tf32(b1.y);
        Bs[0][lrow][lcol + 6] = f2tf32(b1.z); Bs[0][lrow][lcol + 7] = f2tf32(b1.w);
    }
    __syncthreads();

    int buf = 0;
#pragma unroll 1
    for (int it = 0; it < kIters; it++) {
        const bool hasNext = (it + 1) < kIters;
        float4 a0, a1, b0, b1;
        if (hasNext) {
            const int k0 = (it + 1) << 4;
            a0 = *(const float4*)(aRow + k0);
            a1 = *(const float4*)(aRow + k0 + 4);
            b0 = *(const float4*)(bRow + k0);
            b1 = *(const float4*)(bRow + k0 + 4);
        }

#pragma unroll
        for (int ks = 0; ks < 16; ks += 8) {
            uint32_t af[4][4];
#pragma unroll
            for (int mi = 0; mi < 4; mi++) {
                const int r = wm + mi * 16;
                af[mi][0] = As[buf][r + g][ks + t];
                af[mi][1] = As[buf][r + g + 8][ks + t];
                af[mi][2] = As[buf][r + g][ks + t + 4];
                af[mi][3] = As[buf][r + g + 8][ks + t + 4];
            }
            uint32_t bfr[4][2];
#pragma unroll
            for (int ni = 0; ni < 4; ni++) {
                const int c = wn + ni * 8;
                bfr[ni][0] = Bs[buf][c + g][ks + t];
                bfr[ni][1] = Bs[buf][c + g][ks + t + 4];
            }
#pragma unroll
            for (int mi = 0; mi < 4; mi++)
#pragma unroll
                for (int ni = 0; ni < 4; ni++)
                    mma_tf32(acc[mi][ni], af[mi][0], af[mi][1], af[mi][2], af[mi][3],
                             bfr[ni][0], bfr[ni][1]);
        }

        if (hasNext) {
            const int nb = buf ^ 1;
            As[nb][lrow][lcol + 0] = f2tf32(a0.x); As[nb][lrow][lcol + 1] = f2tf32(a0.y);
            As[nb][lrow][lcol + 2] = f2tf32(a0.z); As[nb][lrow][lcol + 3] = f2tf32(a0.w);
            As[nb][lrow][lcol + 4] = f2tf32(a1.x); As[nb][lrow][lcol + 5] = f2tf32(a1.y);
            As[nb][lrow][lcol + 6] = f2tf32(a1.z); As[nb][lrow][lcol + 7] = f2tf32(a1.w);
            Bs[nb][lrow][lcol + 0] = f2tf32(b0.x); Bs[nb][lrow][lcol + 1] = f2tf32(b0.y);
            Bs[nb][lrow][lcol + 2] = f2tf32(b0.z); Bs[nb][lrow][lcol + 3] = f2tf32(b0.w);
            Bs[nb][lrow][lcol + 4] = f2tf32(b1.x); Bs[nb][lrow][lcol + 5] = f2tf32(b1.y);
            Bs[nb][lrow][lcol + 6] = f2tf32(b1.z); Bs[nb][lrow][lcol + 7] = f2tf32(b1.w);
            __syncthreads();
            buf = nb;
        }
    }

#pragma unroll
    for (int ni = 0; ni < 4; ni++) {
        const int cc = bn + wn + ni * 8 + 2 * t;
        float2 bv = make_float2(0.f, 0.f);
        if (bias) bv = *(const float2*)(bias + cc);
#pragma unroll
        for (int mi = 0; mi < 4; mi++) {
            const int rr = bm + wm + mi * 16 + g;
            float2 c0, c1;
            c0.x = acc[mi][ni][0] + bv.x; c0.y = acc[mi][ni][1] + bv.y;
            c1.x = acc[mi][ni][2] + bv.x; c1.y = acc[mi][ni][3] + bv.y;
            *(float2*)(C + (size_t)rr * N + cc) = c0;
            *(float2*)(C + (size_t)(rr + 8) * N + cc) = c1;
        }
    }
}

// ---------------------------------------------------------------------------
// RoPE + tf32 conditioning:
//   q: rotate, fold in ATT_SCALE, round to tf32-clean fp32
//   k: rotate, round to tf32-clean fp32
//   v: round to tf32-clean fp32 (no rotation)
// Flash then feeds raw bits to tf32 MMAs (truncation is exact on clean values).
// ---------------------------------------------------------------------------
__global__ void rope_kernel(const float* __restrict__ fc, const float* __restrict__ fs)
{
    const int NQ = MROWS * HH * 64;
    const int NK = MROWS * KVH * 64;
    int idx = blockIdx.x * 256 + threadIdx.x;
    if (idx < NQ) {
        int d = idx & 63;
        int h = (idx >> 6) % HH;
        int row = idx / (64 * HH);
        int s = row & (SS - 1);
        float c = fc[s * 64 + d], sn = fs[s * 64 + d];
        float* p = g_q + (size_t)row * QN + h * HDIM + 2 * d;
        float xr = p[0], xi = p[1];
        p[0] = tf32r(ATT_SCALE * (xr * c - xi * sn));
        p[1] = tf32r(ATT_SCALE * (xr * sn + xi * c));
    } else if (idx < NQ + NK) {
        int j = idx - NQ;
        int d = j & 63;
        int h = (j >> 6) & 3;
        int row = j >> 8;
        int s = row & (SS - 1);
        float c = fc[s * 64 + d], sn = fs[s * 64 + d];
        float* p = g_k + (size_t)row * KN + h * HDIM + 2 * d;
        float xr = p[0], xi = p[1];
        p[0] = tf32r(xr * c - xi * sn);
        p[1] = tf32r(xr * sn + xi * c);
    } else {
        int j = idx - NQ - NK;
        int d = j & 63;
        int h = (j >> 6) & 3;
        int row = j >> 8;
        float* p = g_v + (size_t)row * KN + h * HDIM + 2 * d;
        p[0] = tf32r(p[0]);
        p[1] = tf32r(p[1]);
    }
}

// ---------------------------------------------------------------------------
// Flash attention on tf32 tensor cores.
// BM=128, BN=64, HD=128. 256 threads = 8 warps; warp w owns rows [w*16, w*16+16)
// across the FULL 64-col key tile (softmax reductions stay in 4-lane groups).
// Q: register A-fragments (loaded once). K: smem [64][132]. V: smem [64][136].
// P: per-warp smem [128][76] round-trip (warp-local, __syncwarp only).
// All pad strides chosen for conflict-free fragment LDS.
// ---------------------------------------------------------------------------
#define KS_W 132
#define VS_W 136
#define PS_W 76
#define FLASH_SMEM_WORDS (64*KS_W + 64*VS_W + 128*PS_W)   // 26880 words = 107520 B

__global__ __launch_bounds__(256) void flash_tc()
{
    extern __shared__ uint32_t smf[];
    uint32_t* Ks = smf;                       // [64][KS_W]
    uint32_t* Vs = smf + 64 * KS_W;           // [64][VS_W]
    uint32_t* Ps = smf + 64 * KS_W + 64 * VS_W; // [128][PS_W]

    const int m0 = (gridDim.x - 1 - blockIdx.x) * 128;   // heavy blocks first
    const int h = blockIdx.y;
    const int b = blockIdx.z;
    const int kvh = h / NREP;
    const int tid = threadIdx.x;
    const int W = tid >> 5;
    const int lane = tid & 31;
    const int g = lane >> 2;
    const int t = lane & 3;

    // Q A-fragments: rows m0+W*16+{g, g+8}, cols ks*8+{t, t+4}. Values are
    // already ATT_SCALE-scaled and tf32-clean (rope pass), so raw bits are fed
    // to the MMA directly.
    const float* qb = g_q + (size_t)(b * SS + m0 + W * 16) * QN + h * HDIM;
    uint32_t qf[16][4];
#pragma unroll
    for (int ks = 0; ks < 16; ks++) {
        qf[ks][0] = __float_as_uint(qb[(size_t)g * QN + ks * 8 + t]);
        qf[ks][1] = __float_as_uint(qb[(size_t)(g + 8) * QN + ks * 8 + t]);
        qf[ks][2] = __float_as_uint(qb[(size_t)g * QN + ks * 8 + t + 4]);
        qf[ks][3] = __float_as_uint(qb[(size_t)(g + 8) * QN + ks * 8 + t + 4]);
    }

    float accO[16][4];
#pragma unroll
    for (int nf = 0; nf < 16; nf++)
#pragma unroll
        for (int e = 0; e < 4; e++) accO[nf][e] = 0.f;
    float mrow[2] = {-1e30f, -1e30f};
    float lrow[2] = {0.f, 0.f};

    const int prow0 = (W * 16 + g) * PS_W;

    const int jcount = m0 / 64 + 2;   // causal: key tiles 0..(m0+64)/64
    for (int jt = 0; jt < jcount; jt++) {
        const int t0 = jt * 64;
        __syncthreads();   // previous PV consumed Ks/Vs

        // Load K,V tiles (values tf32-clean fp32; copy raw, 16B vectors)
        const float* kb = g_k + (size_t)(b * SS + t0) * KN + kvh * HDIM;
        const float* vb = g_v + (size_t)(b * SS + t0) * KN + kvh * HDIM;
#pragma unroll
        for (int it = 0; it < 8; it++) {
            const int e = it * 256 + tid;
            const int r = e >> 5;
            const int d4 = (e & 31) << 2;
            *(uint4*)&Ks[r * KS_W + d4] = *(const uint4*)(kb + (size_t)r * KN + d4);
            *(uint4*)&Vs[r * VS_W + d4] = *(const uint4*)(vb + (size_t)r * KN + d4);
        }
        __syncthreads();

        // ---- QK^T: S[16 rows][64 cols] per warp, fp32 accum
        float sacc[8][4];
#pragma unroll
        for (int nf = 0; nf < 8; nf++)
#pragma unroll
            for (int e = 0; e < 4; e++) sacc[nf][e] = 0.f;

#pragma unroll
        for (int ks = 0; ks < 16; ks++) {
#pragma unroll
            for (int nf = 0; nf < 8; nf++) {
                const uint32_t b0 = Ks[(nf * 8 + g) * KS_W + ks * 8 + t];
                const uint32_t b1 = Ks[(nf * 8 + g) * KS_W + ks * 8 + t + 4];
                mma_tf32(sacc[nf], qf[ks][0], qf[ks][1], qf[ks][2], qf[ks][3], b0, b1);
            }
        }

        // ---- causal mask (only last two key tiles intersect the diagonal)
        if (jt >= jcount - 2) {
            const int r0 = m0 + W * 16 + g;
            const int r1 = r0 + 8;
#pragma unroll
            for (int nf = 0; nf < 8; nf++) {
                const int c0 = t0 + nf * 8 + 2 * t;
                if (c0 > r0)     sacc[nf][0] = -1e30f;
                if (c0 + 1 > r0) sacc[nf][1] = -1e30f;
                if (c0 > r1)     sacc[nf][2] = -1e30f;
                if (c0 + 1 > r1) sacc[nf][3] = -1e30f;
            }
        }

        // ---- online softmax (rows live in 4-lane shfl groups)
        float alpha[2];
#pragma unroll
        for (int i = 0; i < 2; i++) {
            float rm = -1e30f;
#pragma unroll
            for (int nf = 0; nf < 8; nf++)
                rm = fmaxf(rm, fmaxf(sacc[nf][2 * i], sacc[nf][2 * i + 1]));
            rm = fmaxf(rm, __shfl_xor_sync(0xffffffffu, rm, 1));
            rm = fmaxf(rm, __shfl_xor_sync(0xffffffffu, rm, 2));
            const float mn = fmaxf(mrow[i], rm);
            alpha[i] = __expf(mrow[i] - mn);
            float rs = 0.f;
#pragma unroll
            for (int nf = 0; nf < 8; nf++) {
                const float e0 = __expf(sacc[nf][2 * i] - mn);
                const float e1 = __expf(sacc[nf][2 * i + 1] - mn);
                sacc[nf][2 * i] = e0;
                sacc[nf][2 * i + 1] = e1;
                rs += e0 + e1;
            }
            rs += __shfl_xor_sync(0xffffffffu, rs, 1);
            rs += __shfl_xor_sync(0xffffffffu, rs, 2);
            lrow[i] = lrow[i] * alpha[i] + rs;
            mrow[i] = mn;
        }
#pragma unroll
        for (int nf = 0; nf < 16; nf++) {
            accO[nf][0] *= alpha[0]; accO[nf][1] *= alpha[0];
            accO[nf][2] *= alpha[1]; accO[nf][3] *= alpha[1];
        }

        // ---- stage P (tf32) in warp-private smem rows
#pragma unroll
        for (int nf = 0; nf < 8; nf++) {
            const int c = nf * 8 + 2 * t;
            Ps[prow0 + c]                = f2tf32(sacc[nf][0]);
            Ps[prow0 + c + 1]            = f2tf32(sacc[nf][1]);
            Ps[prow0 + 8 * PS_W + c]     = f2tf32(sacc[nf][2]);
            Ps[prow0 + 8 * PS_W + c + 1] = f2tf32(sacc[nf][3]);
        }
        __syncwarp();

        // ---- P·V: O[16 rows][128 d] per warp
#pragma unroll
        for (int ks = 0; ks < 8; ks++) {
            const uint32_t a0 = Ps[prow0 + ks * 8 + t];
            const uint32_t a1 = Ps[prow0 + 8 * PS_W + ks * 8 + t];
            const uint32_t a2 = Ps[prow0 + ks * 8 + t + 4];
            const uint32_t a3 = Ps[prow0 + 8 * PS_W + ks * 8 + t + 4];
#pragma unroll
            for (int nf = 0; nf < 16; nf++) {
                const uint32_t b0 = Vs[(ks * 8 + t) * VS_W + nf * 8 + g];
                const uint32_t b1 = Vs[(ks * 8 + t + 4) * VS_W + nf * 8 + g];
                mma_tf32(accO[nf], a0, a1, a2, a3, b0, b1);
            }
        }
        __syncwarp();   // Ps reads done before next iteration overwrites
    }

    // ---- finalize
    const float inv0 = 1.f / lrow[0];
    const float inv1 = 1.f / lrow[1];
    float* ob = g_o + (size_t)(b * SS + m0 + W * 16) * QN + h * HDIM;
#pragma unroll
    for (int nf = 0; nf < 16; nf++) {
        const int c = nf * 8 + 2 * t;
        *(float2*)(ob + (size_t)g * QN + c) =
            make_float2(accO[nf][0] * inv0, accO[nf][1] * inv0);
        *(float2*)(ob + (size_t)(g + 8) * QN + c) =
            make_float2(accO[nf][2] * inv1, accO[nf][3] * inv1);
    }
}

// ---------------------------------------------------------------------------
// kernel_launch
// ---------------------------------------------------------------------------
extern "C" void kernel_launch(void* const* d_in, const int* in_sizes, int n_in,
                              void* d_out, int out_size)
{
    const float* x    = (const float*)d_in[0];
    const float* wq_w = (const float*)d_in[1];
    const float* wq_b = (const float*)d_in[2];
    const float* wk_w = (const float*)d_in[3];
    const float* wk_b = (const float*)d_in[4];
    const float* wv_w = (const float*)d_in[5];
    const float* wv_b = (const float*)d_in[6];
    const float* wo_w = (const float*)d_in[7];
    const float* fc   = (const float*)d_in[10];
    const float* fs   = (const float*)d_in[11];
    float* out = (float*)d_out;

    const int flash_smem = FLASH_SMEM_WORDS * 4;  // 107,520 bytes
    cudaFuncSetAttribute(flash_tc, cudaFuncAttributeMaxDynamicSharedMemorySize, flash_smem);

    // QKV projections on tf32 tensor cores
    gemm_tf32<<<dim3(QN / 128, MROWS / 128), 256>>>(x, BUF_EXT, wq_w, wq_b, nullptr, BUF_Q, MROWS, QN, DD);
    gemm_tf32<<<dim3(KN / 128, MROWS / 128), 256>>>(x, BUF_EXT, wk_w, wk_b, nullptr, BUF_K, MROWS, KN, DD);
    gemm_tf32<<<dim3(KN / 128, MROWS / 128), 256>>>(x, BUF_EXT, wv_w, wv_b, nullptr, BUF_V, MROWS, KN, DD);

    // RoPE + tf32 conditioning of q (scaled), k, v
    rope_kernel<<<(MROWS * HH * 64 + 2 * MROWS * KVH * 64) / 256, 256>>>(fc, fs);

    // Causal GQA flash attention on tensor cores: g_q,g_k,g_v -> g_o
    flash_tc<<<dim3(SS / 128, HH, BB), 256, flash_smem>>>();

    // Output projection: g_o @ wo_w^T -> out
    gemm_tf32<<<dim3(QN / 128, MROWS / 128), 256>>>(nullptr, BUF_O, wo_w, nullptr, out, BUF_EXT, MROWS, QN, DD);
}

// round 9
// speedup vs baseline: 2.3785x; 1.4211x over previous
#include <cuda_runtime.h>
#include <cuda_bf16.h>
#include <cstdint>
#include <cstddef>

// Problem constants (fixed by setup_inputs)
#define BB 2
#define SS 2048
#define DD 3584
#define HH 28
#define KVH 4
#define HDIM 128
#define NREP 7
#define MROWS (BB*SS)          // 4096
#define QN (HH*HDIM)           // 3584
#define KN (KVH*HDIM)          // 512
#define ATT_SCALE 0.08838834764831845f

// ---------------------------------------------------------------------------
// Scratch (device globals)
// ---------------------------------------------------------------------------
__device__ float g_q[(size_t)MROWS * QN];   // post-rope: scaled + tf32-clean
__device__ float g_k[(size_t)MROWS * KN];   // post-rope: tf32-clean
__device__ float g_v[(size_t)MROWS * KN];   // tf32-clean
__device__ float g_o[(size_t)MROWS * QN];   // attention output (tf32-clean)
// tf32-clean copies of GEMM operands (filled once by convert_tf32)
__device__ float g_xa[(size_t)MROWS * DD];
__device__ float g_wq[(size_t)QN * DD];
__device__ float g_wk[(size_t)KN * DD];
__device__ float g_wv[(size_t)KN * DD];
__device__ float g_wo[(size_t)DD * QN];

// GEMM operand selectors (device globals can't be passed as host pointers)
#define SRC_XA 0
#define SRC_O  1
#define SRC_WQ 2
#define SRC_WK 3
#define SRC_WV 4
#define SRC_WO 5
#define DST_EXT 0
#define DST_Q   1
#define DST_K   2
#define DST_V   3

__device__ __forceinline__ const float* gsrc(int sel) {
    switch (sel) {
        case SRC_XA: return g_xa;
        case SRC_O:  return g_o;
        case SRC_WQ: return g_wq;
        case SRC_WK: return g_wk;
        case SRC_WV: return g_wv;
        default:     return g_wo;
    }
}
__device__ __forceinline__ float* gdst(int sel, float* ext) {
    switch (sel) {
        case DST_Q: return g_q;
        case DST_K: return g_k;
        case DST_V: return g_v;
        default:    return ext;
    }
}

__device__ __forceinline__ uint32_t f2tf32(float x) {
    uint32_t r;
    asm("cvt.rna.tf32.f32 %0, %1;" : "=r"(r) : "f"(x));
    return r;
}
__device__ __forceinline__ float tf32r(float x) {
    return __uint_as_float(f2tf32(x));
}

__device__ __forceinline__ void mma_tf32(float acc[4],
                                         uint32_t a0, uint32_t a1, uint32_t a2, uint32_t a3,
                                         uint32_t b0, uint32_t b1) {
    asm volatile(
        "mma.sync.aligned.m16n8k8.row.col.f32.tf32.tf32.f32 "
        "{%0,%1,%2,%3}, {%4,%5,%6,%7}, {%8,%9}, {%0,%1,%2,%3};\n"
        : "+f"(acc[0]), "+f"(acc[1]), "+f"(acc[2]), "+f"(acc[3])
        : "r"(a0), "r"(a1), "r"(a2), "r"(a3), "r"(b0), "r"(b1));
}

__device__ __forceinline__ void cp_async16(uint32_t saddr, const void* gaddr) {
    asm volatile("cp.async.cg.shared.global [%0], [%1], 16;\n"
                 :: "r"(saddr), "l"(gaddr));
}

// ---------------------------------------------------------------------------
// One-shot tf32 conditioning of GEMM operands (x + 4 weights).
// All segment sizes are multiples of 4; grid covers the total exactly.
// ---------------------------------------------------------------------------
#define N_XA ((size_t)MROWS * DD)   // 14,680,064
#define N_WQ ((size_t)QN * DD)      // 12,845,056
#define N_WK ((size_t)KN * DD)      //  1,835,008
#define N_WV ((size_t)KN * DD)
#define N_WO ((size_t)DD * QN)      // 12,845,056
#define N_CVT_TOTAL (N_XA + N_WQ + N_WK + N_WV + N_WO)   // 44,040,192
#define CVT_BLOCKS ((int)(N_CVT_TOTAL / 4 / 256))        // 43008

__global__ void convert_tf32(const float* __restrict__ x,
                             const float* __restrict__ wq,
                             const float* __restrict__ wk,
                             const float* __restrict__ wv,
                             const float* __restrict__ wo)
{
    size_t idx = ((size_t)blockIdx.x * 256 + threadIdx.x) * 4;
    const float* src;
    float* dst;
    size_t off;
    if (idx < N_XA)                          { src = x;  dst = g_xa; off = idx; }
    else if (idx < N_XA + N_WQ)              { src = wq; dst = g_wq; off = idx - N_XA; }
    else if (idx < N_XA + N_WQ + N_WK)       { src = wk; dst = g_wk; off = idx - N_XA - N_WQ; }
    else if (idx < N_XA + N_WQ + N_WK + N_WV){ src = wv; dst = g_wv; off = idx - N_XA - N_WQ - N_WK; }
    else                                     { src = wo; dst = g_wo; off = idx - N_XA - N_WQ - N_WK - N_WV; }
    float4 v = *(const float4*)(src + off);
    v.x = tf32r(v.x); v.y = tf32r(v.y); v.z = tf32r(v.z); v.w = tf32r(v.w);
    *(float4*)(dst + off) = v;
}

// ---------------------------------------------------------------------------
// Pipelined NT GEMM on tf32 tensor cores.
// C[m,n] = sum_k A[m,k]*B[n,k] (+bias[n]).  A,B already tf32-clean.
// 128x128 tile, BK=32, 3-stage cp.async pipeline, 256 threads = 8 warps (2x4),
// each warp 64x32 via 4x4 m16n8k8 fragments. Smem rows stride 36 words:
// 36 = 4 mod 32 => fragment LDS banks (4g+t) all distinct; 144B rows keep
// 16B cp.async alignment. Requires M%128==0, N%128==0, K%32==0, K/32>=2.
// ---------------------------------------------------------------------------
#define GSTAGES 3
#define GA_W 36
#define G_STAGE_WORDS (128 * GA_W * 2)               // 9216 words (A then B)
#define GEMM_SMEM_BYTES (GSTAGES * G_STAGE_WORDS * 4) // 110,592 B

__global__ __launch_bounds__(256) void gemm_pipe(
    int a_sel, int b_sel,
    const float* __restrict__ bias,
    float* __restrict__ Cext, int c_sel,
    int M, int N, int K)
{
    const float* A = gsrc(a_sel);
    const float* B = gsrc(b_sel);
    float* C = gdst(c_sel, Cext);

    extern __shared__ uint32_t smg[];
    const uint32_t smem_u32 = (uint32_t)__cvta_generic_to_shared(smg);

    const int bm = blockIdx.y * 128;
    const int bn = blockIdx.x * 128;
    const int tid = threadIdx.x;
    const int warp = tid >> 5;
    const int lane = tid & 31;
    const int g = lane >> 2;
    const int t = lane & 3;
    const int wm = (warp >> 2) * 64;
    const int wn = (warp & 3) * 32;

    const int kIters = K >> 5;   // BK=32; all uses have K=3584 -> 112

    // cp.async issue for one stage: A tile 128x32 + B tile 128x32, 16B chunks.
    auto issue_stage = [&](int it, int stg) {
        const int k0 = it << 5;
        const uint32_t sbase = smem_u32 + (uint32_t)stg * G_STAGE_WORDS * 4;
#pragma unroll
        for (int i = 0; i < 4; i++) {
            const int chunk = i * 256 + tid;        // 0..1023
            const int row = chunk >> 3;
            const int c4 = (chunk & 7) << 2;
            cp_async16(sbase + (row * GA_W + c4) * 4,
                       A + (size_t)(bm + row) * K + k0 + c4);
        }
#pragma unroll
        for (int i = 0; i < 4; i++) {
            const int chunk = i * 256 + tid;
            const int row = chunk >> 3;
            const int c4 = (chunk & 7) << 2;
            cp_async16(sbase + (128 * GA_W + row * GA_W + c4) * 4,
                       B + (size_t)(bn + row) * K + k0 + c4);
        }
        asm volatile("cp.async.commit_group;\n" ::: "memory");
    };

    float acc[4][4][4];
#pragma unroll
    for (int mi = 0; mi < 4; mi++)
#pragma unroll
        for (int ni = 0; ni < 4; ni++)
#pragma unroll
            for (int e = 0; e < 4; e++) acc[mi][ni][e] = 0.f;

    issue_stage(0, 0);
    issue_stage(1, 1);

#pragma unroll 1
    for (int it = 0; it < kIters; it++) {
        if (it == kIters - 1)
            asm volatile("cp.async.wait_group 0;\n" ::: "memory");
        else
            asm volatile("cp.async.wait_group 1;\n" ::: "memory");
        __syncthreads();

        if (it + 2 < kIters) issue_stage(it + 2, (it + 2) % GSTAGES);

        const uint32_t* As_ = smg + (it % GSTAGES) * G_STAGE_WORDS;
        const uint32_t* Bs_ = As_ + 128 * GA_W;

#pragma unroll
        for (int ks = 0; ks < 32; ks += 8) {
            uint32_t af[4][4];
#pragma unroll
            for (int mi = 0; mi < 4; mi++) {
                const int r = wm + mi * 16;
                af[mi][0] = As_[(r + g) * GA_W + ks + t];
                af[mi][1] = As_[(r + g + 8) * GA_W + ks + t];
                af[mi][2] = As_[(r + g) * GA_W + ks + t + 4];
                af[mi][3] = As_[(r + g + 8) * GA_W + ks + t + 4];
            }
            uint32_t bfr[4][2];
#pragma unroll
            for (int ni = 0; ni < 4; ni++) {
                const int c = wn + ni * 8;
                bfr[ni][0] = Bs_[(c + g) * GA_W + ks + t];
                bfr[ni][1] = Bs_[(c + g) * GA_W + ks + t + 4];
            }
#pragma unroll
            for (int mi = 0; mi < 4; mi++)
#pragma unroll
                for (int ni = 0; ni < 4; ni++)
                    mma_tf32(acc[mi][ni], af[mi][0], af[mi][1], af[mi][2], af[mi][3],
                             bfr[ni][0], bfr[ni][1]);
        }
        __syncthreads();   // all warps done with this stage before it is refilled
    }

    // Epilogue: rows (g, g+8), cols (2t, 2t+1) per fragment, plus bias
#pragma unroll
    for (int ni = 0; ni < 4; ni++) {
        const int cc = bn + wn + ni * 8 + 2 * t;
        float2 bv = make_float2(0.f, 0.f);
        if (bias) bv = *(const float2*)(bias + cc);
#pragma unroll
        for (int mi = 0; mi < 4; mi++) {
            const int rr = bm + wm + mi * 16 + g;
            *(float2*)(C + (size_t)rr * N + cc) =
                make_float2(acc[mi][ni][0] + bv.x, acc[mi][ni][1] + bv.y);
            *(float2*)(C + (size_t)(rr + 8) * N + cc) =
                make_float2(acc[mi][ni][2] + bv.x, acc[mi][ni][3] + bv.y);
        }
    }
}

// ---------------------------------------------------------------------------
// RoPE + tf32 conditioning of q (ATT_SCALE folded), k, v.
// ---------------------------------------------------------------------------
__global__ void rope_kernel(const float* __restrict__ fc, const float* __restrict__ fs)
{
    const int NQ = MROWS * HH * 64;
    const int NK = MROWS * KVH * 64;
    int idx = blockIdx.x * 256 + threadIdx.x;
    if (idx < NQ) {
        int d = idx & 63;
        int h = (idx >> 6) % HH;
        int row = idx / (64 * HH);
        int s = row & (SS - 1);
        float c = fc[s * 64 + d], sn = fs[s * 64 + d];
        float* p = g_q + (size_t)row * QN + h * HDIM + 2 * d;
        float xr = p[0], xi = p[1];
        p[0] = tf32r(ATT_SCALE * (xr * c - xi * sn));
        p[1] = tf32r(ATT_SCALE * (xr * sn + xi * c));
    } else if (idx < NQ + NK) {
        int j = idx - NQ;
        int d = j & 63;
        int h = (j >> 6) & 3;
        int row = j >> 8;
        int s = row & (SS - 1);
        float c = fc[s * 64 + d], sn = fs[s * 64 + d];
        float* p = g_k + (size_t)row * KN + h * HDIM + 2 * d;
        float xr = p[0], xi = p[1];
        p[0] = tf32r(xr * c - xi * sn);
        p[1] = tf32r(xr * sn + xi * c);
    } else {
        int j = idx - NQ - NK;
        int d = j & 63;
        int h = (j >> 6) & 3;
        int row = j >> 8;
        float* p = g_v + (size_t)row * KN + h * HDIM + 2 * d;
        p[0] = tf32r(p[0]);
        p[1] = tf32r(p[1]);
    }
}

// ---------------------------------------------------------------------------
// Flash attention on tf32 tensor cores (passing R7 design; finalize writes
// tf32-clean values so the O-projection GEMM needs no conversion).
// ---------------------------------------------------------------------------
#define KS_W 132
#define VS_W 136
#define PS_W 76
#define FLASH_SMEM_WORDS (64*KS_W + 64*VS_W + 128*PS_W)   // 26880 words

__global__ __launch_bounds__(256) void flash_tc()
{
    extern __shared__ uint32_t smf[];
    uint32_t* Ks = smf;
    uint32_t* Vs = smf + 64 * KS_W;
    uint32_t* Ps = smf + 64 * KS_W + 64 * VS_W;

    const int m0 = (gridDim.x - 1 - blockIdx.x) * 128;
    const int h = blockIdx.y;
    const int b = blockIdx.z;
    const int kvh = h / NREP;
    const int tid = threadIdx.x;
    const int W = tid >> 5;
    const int lane = tid & 31;
    const int g = lane >> 2;
    const int t = lane & 3;

    const float* qb = g_q + (size_t)(b * SS + m0 + W * 16) * QN + h * HDIM;
    uint32_t qf[16][4];
#pragma unroll
    for (int ks = 0; ks < 16; ks++) {
        qf[ks][0] = __float_as_uint(qb[(size_t)g * QN + ks * 8 + t]);
        qf[ks][1] = __float_as_uint(qb[(size_t)(g + 8) * QN + ks * 8 + t]);
        qf[ks][2] = __float_as_uint(qb[(size_t)g * QN + ks * 8 + t + 4]);
        qf[ks][3] = __float_as_uint(qb[(size_t)(g + 8) * QN + ks * 8 + t + 4]);
    }

    float accO[16][4];
#pragma unroll
    for (int nf = 0; nf < 16; nf++)
#pragma unroll
        for (int e = 0; e < 4; e++) accO[nf][e] = 0.f;
    float mrow[2] = {-1e30f, -1e30f};
    float lrow[2] = {0.f, 0.f};

    const int prow0 = (W * 16 + g) * PS_W;

    const int jcount = m0 / 64 + 2;
    for (int jt = 0; jt < jcount; jt++) {
        const int t0 = jt * 64;
        __syncthreads();

        const float* kb = g_k + (size_t)(b * SS + t0) * KN + kvh * HDIM;
        const float* vb = g_v + (size_t)(b * SS + t0) * KN + kvh * HDIM;
#pragma unroll
        for (int it = 0; it < 8; it++) {
            const int e = it * 256 + tid;
            const int r = e >> 5;
            const int d4 = (e & 31) << 2;
            *(uint4*)&Ks[r * KS_W + d4] = *(const uint4*)(kb + (size_t)r * KN + d4);
            *(uint4*)&Vs[r * VS_W + d4] = *(const uint4*)(vb + (size_t)r * KN + d4);
        }
        __syncthreads();

        float sacc[8][4];
#pragma unroll
        for (int nf = 0; nf < 8; nf++)
#pragma unroll
            for (int e = 0; e < 4; e++) sacc[nf][e] = 0.f;

#pragma unroll
        for (int ks = 0; ks < 16; ks++) {
#pragma unroll
            for (int nf = 0; nf < 8; nf++) {
                const uint32_t b0 = Ks[(nf * 8 + g) * KS_W + ks * 8 + t];
                const uint32_t b1 = Ks[(nf * 8 + g) * KS_W + ks * 8 + t + 4];
                mma_tf32(sacc[nf], qf[ks][0], qf[ks][1], qf[ks][2], qf[ks][3], b0, b1);
            }
        }

        if (jt >= jcount - 2) {
            const int r0 = m0 + W * 16 + g;
            const int r1 = r0 + 8;
#pragma unroll
            for (int nf = 0; nf < 8; nf++) {
                const int c0 = t0 + nf * 8 + 2 * t;
                if (c0 > r0)     sacc[nf][0] = -1e30f;
                if (c0 + 1 > r0) sacc[nf][1] = -1e30f;
                if (c0 > r1)     sacc[nf][2] = -1e30f;
                if (c0 + 1 > r1) sacc[nf][3] = -1e30f;
            }
        }

        float alpha[2];
#pragma unroll
        for (int i = 0; i < 2; i++) {
            float rm = -1e30f;
#pragma unroll
            for (int nf = 0; nf < 8; nf++)
                rm = fmaxf(rm, fmaxf(sacc[nf][2 * i], sacc[nf][2 * i + 1]));
            rm = fmaxf(rm, __shfl_xor_sync(0xffffffffu, rm, 1));
            rm = fmaxf(rm, __shfl_xor_sync(0xffffffffu, rm, 2));
            const float mn = fmaxf(mrow[i], rm);
            alpha[i] = __expf(mrow[i] - mn);
            float rs = 0.f;
#pragma unroll
            for (int nf = 0; nf < 8; nf++) {
                const float e0 = __expf(sacc[nf][2 * i] - mn);
                const float e1 = __expf(sacc[nf][2 * i + 1] - mn);
                sacc[nf][2 * i] = e0;
                sacc[nf][2 * i + 1] = e1;
                rs += e0 + e1;
            }
            rs += __shfl_xor_sync(0xffffffffu, rs, 1);
            rs += __shfl_xor_sync(0xffffffffu, rs, 2);
            lrow[i] = lrow[i] * alpha[i] + rs;
            mrow[i] = mn;
        }
#pragma unroll
        for (int nf = 0; nf < 16; nf++) {
            accO[nf][0] *= alpha[0]; accO[nf][1] *= alpha[0];
            accO[nf][2] *= alpha[1]; accO[nf][3] *= alpha[1];
        }

#pragma unroll
        for (int nf = 0; nf < 8; nf++) {
            const int c = nf * 8 + 2 * t;
            Ps[prow0 + c]                = f2tf32(sacc[nf][0]);
            Ps[prow0 + c + 1]            = f2tf32(sacc[nf][1]);
            Ps[prow0 + 8 * PS_W + c]     = f2tf32(sacc[nf][2]);
            Ps[prow0 + 8 * PS_W + c + 1] = f2tf32(sacc[nf][3]);
        }
        __syncwarp();

#pragma unroll
        for (int ks = 0; ks < 8; ks++) {
            const uint32_t a0 = Ps[prow0 + ks * 8 + t];
            const uint32_t a1 = Ps[prow0 + 8 * PS_W + ks * 8 + t];
            const uint32_t a2 = Ps[prow0 + ks * 8 + t + 4];
            const uint32_t a3 = Ps[prow0 + 8 * PS_W + ks * 8 + t + 4];
#pragma unroll
            for (int nf = 0; nf < 16; nf++) {
                const uint32_t b0 = Vs[(ks * 8 + t) * VS_W + nf * 8 + g];
                const uint32_t b1 = Vs[(ks * 8 + t + 4) * VS_W + nf * 8 + g];
                mma_tf32(accO[nf], a0, a1, a2, a3, b0, b1);
            }
        }
        __syncwarp();
    }

    const float inv0 = 1.f / lrow[0];
    const float inv1 = 1.f / lrow[1];
    float* ob = g_o + (size_t)(b * SS + m0 + W * 16) * QN + h * HDIM;
#pragma unroll
    for (int nf = 0; nf < 16; nf++) {
        const int c = nf * 8 + 2 * t;
        *(float2*)(ob + (size_t)g * QN + c) =
            make_float2(tf32r(accO[nf][0] * inv0), tf32r(accO[nf][1] * inv0));
        *(float2*)(ob + (size_t)(g + 8) * QN + c) =
            make_float2(tf32r(accO[nf][2] * inv1), tf32r(accO[nf][3] * inv1));
    }
}

// ---------------------------------------------------------------------------
// kernel_launch
// ---------------------------------------------------------------------------
extern "C" void kernel_launch(void* const* d_in, const int* in_sizes, int n_in,
                              void* d_out, int out_size)
{
    const float* x    = (const float*)d_in[0];
    const float* wq_w = (const float*)d_in[1];
    const float* wq_b = (const float*)d_in[2];
    const float* wk_w = (const float*)d_in[3];
    const float* wk_b = (const float*)d_in[4];
    const float* wv_w = (const float*)d_in[5];
    const float* wv_b = (const float*)d_in[6];
    const float* wo_w = (const float*)d_in[7];
    const float* fc   = (const float*)d_in[10];
    const float* fs   = (const float*)d_in[11];
    float* out = (float*)d_out;

    const int flash_smem = FLASH_SMEM_WORDS * 4;   // 107,520 B
    cudaFuncSetAttribute(flash_tc, cudaFuncAttributeMaxDynamicSharedMemorySize, flash_smem);
    cudaFuncSetAttribute(gemm_pipe, cudaFuncAttributeMaxDynamicSharedMemorySize, GEMM_SMEM_BYTES);

    // tf32-condition all GEMM operands once
    convert_tf32<<<CVT_BLOCKS, 256>>>(x, wq_w, wk_w, wv_w, wo_w);

    // QKV projections (pipelined tf32 tensor-core GEMM)
    gemm_pipe<<<dim3(QN / 128, MROWS / 128), 256, GEMM_SMEM_BYTES>>>(
        SRC_XA, SRC_WQ, wq_b, nullptr, DST_Q, MROWS, QN, DD);
    gemm_pipe<<<dim3(KN / 128, MROWS / 128), 256, GEMM_SMEM_BYTES>>>(
        SRC_XA, SRC_WK, wk_b, nullptr, DST_K, MROWS, KN, DD);
    gemm_pipe<<<dim3(KN / 128, MROWS / 128), 256, GEMM_SMEM_BYTES>>>(
        SRC_XA, SRC_WV, wv_b, nullptr, DST_V, MROWS, KN, DD);

    // RoPE + tf32 conditioning of q (scaled), k, v
    rope_kernel<<<(MROWS * HH * 64 + 2 * MROWS * KVH * 64) / 256, 256>>>(fc, fs);

    // Causal GQA flash attention on tensor cores: g_q,g_k,g_v -> g_o
    flash_tc<<<dim3(SS / 128, HH, BB), 256, flash_smem>>>();

    // Output projection: g_o @ wo_w^T -> out
    gemm_pipe<<<dim3(QN / 128, MROWS / 128), 256, GEMM_SMEM_BYTES>>>(
        SRC_O, SRC_WO, nullptr, out, DST_EXT, MROWS, QN, DD);
}

// round 10
// speedup vs baseline: 2.3943x; 1.0067x over previous
#include <cuda_runtime.h>
#include <cuda_bf16.h>
#include <cstdint>
#include <cstddef>

// Problem constants (fixed by setup_inputs)
#define BB 2
#define SS 2048
#define DD 3584
#define HH 28
#define KVH 4
#define HDIM 128
#define NREP 7
#define MROWS (BB*SS)          // 4096
#define QN (HH*HDIM)           // 3584
#define KN (KVH*HDIM)          // 512
#define ATT_SCALE 0.08838834764831845f

// ---------------------------------------------------------------------------
// Scratch (device globals)
// ---------------------------------------------------------------------------
__device__ float g_q[(size_t)MROWS * QN];   // post-rope: scaled + tf32-clean
__device__ float g_k[(size_t)MROWS * KN];   // post-rope: tf32-clean
__device__ float g_v[(size_t)MROWS * KN];   // tf32-clean
__device__ float g_o[(size_t)MROWS * QN];   // attention output (tf32-clean)
// tf32-clean copies of GEMM operands (filled once by convert_tf32)
__device__ float g_xa[(size_t)MROWS * DD];
__device__ float g_wq[(size_t)QN * DD];
__device__ float g_wk[(size_t)KN * DD];
__device__ float g_wv[(size_t)KN * DD];
__device__ float g_wo[(size_t)DD * QN];

// GEMM operand selectors (device globals can't be passed as host pointers)
#define SRC_XA 0
#define SRC_O  1
#define SRC_WQ 2
#define SRC_WK 3
#define SRC_WV 4
#define SRC_WO 5
#define DST_EXT 0
#define DST_Q   1
#define DST_K   2
#define DST_V   3

__device__ __forceinline__ const float* gsrc(int sel) {
    switch (sel) {
        case SRC_XA: return g_xa;
        case SRC_O:  return g_o;
        case SRC_WQ: return g_wq;
        case SRC_WK: return g_wk;
        case SRC_WV: return g_wv;
        default:     return g_wo;
    }
}
__device__ __forceinline__ float* gdst(int sel, float* ext) {
    switch (sel) {
        case DST_Q: return g_q;
        case DST_K: return g_k;
        case DST_V: return g_v;
        default:    return ext;
    }
}

__device__ __forceinline__ uint32_t f2tf32(float x) {
    uint32_t r;
    asm("cvt.rna.tf32.f32 %0, %1;" : "=r"(r) : "f"(x));
    return r;
}
__device__ __forceinline__ float tf32r(float x) {
    return __uint_as_float(f2tf32(x));
}

__device__ __forceinline__ void mma_tf32(float acc[4],
                                         uint32_t a0, uint32_t a1, uint32_t a2, uint32_t a3,
                                         uint32_t b0, uint32_t b1) {
    asm volatile(
        "mma.sync.aligned.m16n8k8.row.col.f32.tf32.tf32.f32 "
        "{%0,%1,%2,%3}, {%4,%5,%6,%7}, {%8,%9}, {%0,%1,%2,%3};\n"
        : "+f"(acc[0]), "+f"(acc[1]), "+f"(acc[2]), "+f"(acc[3])
        : "r"(a0), "r"(a1), "r"(a2), "r"(a3), "r"(b0), "r"(b1));
}

__device__ __forceinline__ void cp_async16(uint32_t saddr, const void* gaddr) {
    asm volatile("cp.async.cg.shared.global [%0], [%1], 16;\n"
                 :: "r"(saddr), "l"(gaddr));
}

// ---------------------------------------------------------------------------
// One-shot tf32 conditioning of GEMM operands (x + 4 weights).
// ---------------------------------------------------------------------------
#define N_XA ((size_t)MROWS * DD)   // 14,680,064
#define N_WQ ((size_t)QN * DD)      // 12,845,056
#define N_WK ((size_t)KN * DD)      //  1,835,008
#define N_WV ((size_t)KN * DD)
#define N_WO ((size_t)DD * QN)      // 12,845,056
#define N_CVT_TOTAL (N_XA + N_WQ + N_WK + N_WV + N_WO)   // 44,040,192
#define CVT_BLOCKS ((int)(N_CVT_TOTAL / 4 / 256))        // 43008

__global__ void convert_tf32(const float* __restrict__ x,
                             const float* __restrict__ wq,
                             const float* __restrict__ wk,
                             const float* __restrict__ wv,
                             const float* __restrict__ wo)
{
    size_t idx = ((size_t)blockIdx.x * 256 + threadIdx.x) * 4;
    const float* src;
    float* dst;
    size_t off;
    if (idx < N_XA)                          { src = x;  dst = g_xa; off = idx; }
    else if (idx < N_XA + N_WQ)              { src = wq; dst = g_wq; off = idx - N_XA; }
    else if (idx < N_XA + N_WQ + N_WK)       { src = wk; dst = g_wk; off = idx - N_XA - N_WQ; }
    else if (idx < N_XA + N_WQ + N_WK + N_WV){ src = wv; dst = g_wv; off = idx - N_XA - N_WQ - N_WK; }
    else                                     { src = wo; dst = g_wo; off = idx - N_XA - N_WQ - N_WK - N_WV; }
    float4 v = *(const float4*)(src + off);
    v.x = tf32r(v.x); v.y = tf32r(v.y); v.z = tf32r(v.z); v.w = tf32r(v.w);
    *(float4*)(dst + off) = v;
}

// ---------------------------------------------------------------------------
// Pipelined NT GEMM on tf32 tensor cores.
// 128x128 tile, BK=32, 2-stage cp.async pipeline, 256 threads = 8 warps (2x4),
// each warp 64x32 via 4x4 m16n8k8 fragments. Stride-36 smem rows: conflict-free
// fragment LDS + 16B cp.async alignment. 2 stages = 73,728 B smem so TWO CTAs
// co-reside per SM (16 warps) — cross-CTA interleave replaces the third stage.
// Stage refill for (it+2) is issued AFTER the trailing barrier because with
// 2 stages it aliases the stage just computed.
// Requires M%128==0, N%128==0, K%32==0, K/32>=2.
// ---------------------------------------------------------------------------
#define GSTAGES 2
#define GA_W 36
#define G_STAGE_WORDS (128 * GA_W * 2)                 // 9216 words (A then B)
#define GEMM_SMEM_BYTES (GSTAGES * G_STAGE_WORDS * 4)  // 73,728 B

__global__ __launch_bounds__(256, 2) void gemm_pipe(
    int a_sel, int b_sel,
    const float* __restrict__ bias,
    float* __restrict__ Cext, int c_sel,
    int M, int N, int K)
{
    const float* A = gsrc(a_sel);
    const float* B = gsrc(b_sel);
    float* C = gdst(c_sel, Cext);

    extern __shared__ uint32_t smg[];
    const uint32_t smem_u32 = (uint32_t)__cvta_generic_to_shared(smg);

    const int bm = blockIdx.y * 128;
    const int bn = blockIdx.x * 128;
    const int tid = threadIdx.x;
    const int warp = tid >> 5;
    const int lane = tid & 31;
    const int g = lane >> 2;
    const int t = lane & 3;
    const int wm = (warp >> 2) * 64;
    const int wn = (warp & 3) * 32;

    const int kIters = K >> 5;   // BK=32; all uses have K=3584 -> 112

    // cp.async issue for one stage: A tile 128x32 + B tile 128x32, 16B chunks.
    auto issue_stage = [&](int it, int stg) {
        const int k0 = it << 5;
        const uint32_t sbase = smem_u32 + (uint32_t)stg * G_STAGE_WORDS * 4;
#pragma unroll
        for (int i = 0; i < 4; i++) {
            const int chunk = i * 256 + tid;        // 0..1023
            const int row = chunk >> 3;
            const int c4 = (chunk & 7) << 2;
            cp_async16(sbase + (row * GA_W + c4) * 4,
                       A + (size_t)(bm + row) * K + k0 + c4);
        }
#pragma unroll
        for (int i = 0; i < 4; i++) {
            const int chunk = i * 256 + tid;
            const int row = chunk >> 3;
            const int c4 = (chunk & 7) << 2;
            cp_async16(sbase + (128 * GA_W + row * GA_W + c4) * 4,
                       B + (size_t)(bn + row) * K + k0 + c4);
        }
        asm volatile("cp.async.commit_group;\n" ::: "memory");
    };

    float acc[4][4][4];
#pragma unroll
    for (int mi = 0; mi < 4; mi++)
#pragma unroll
        for (int ni = 0; ni < 4; ni++)
#pragma unroll
            for (int e = 0; e < 4; e++) acc[mi][ni][e] = 0.f;

    issue_stage(0, 0);
    issue_stage(1, 1);

#pragma unroll 1
    for (int it = 0; it < kIters; it++) {
        if (it == kIters - 1)
            asm volatile("cp.async.wait_group 0;\n" ::: "memory");
        else
            asm volatile("cp.async.wait_group 1;\n" ::: "memory");
        __syncthreads();

        const uint32_t* As_ = smg + (it % GSTAGES) * G_STAGE_WORDS;
        const uint32_t* Bs_ = As_ + 128 * GA_W;

#pragma unroll
        for (int ks = 0; ks < 32; ks += 8) {
            uint32_t af[4][4];
#pragma unroll
            for (int mi = 0; mi < 4; mi++) {
                const int r = wm + mi * 16;
                af[mi][0] = As_[(r + g) * GA_W + ks + t];
                af[mi][1] = As_[(r + g + 8) * GA_W + ks + t];
                af[mi][2] = As_[(r + g) * GA_W + ks + t + 4];
                af[mi][3] = As_[(r + g + 8) * GA_W + ks + t + 4];
            }
            uint32_t bfr[4][2];
#pragma unroll
            for (int ni = 0; ni < 4; ni++) {
                const int c = wn + ni * 8;
                bfr[ni][0] = Bs_[(c + g) * GA_W + ks + t];
                bfr[ni][1] = Bs_[(c + g) * GA_W + ks + t + 4];
            }
#pragma unroll
            for (int mi = 0; mi < 4; mi++)
#pragma unroll
                for (int ni = 0; ni < 4; ni++)
                    mma_tf32(acc[mi][ni], af[mi][0], af[mi][1], af[mi][2], af[mi][3],
                             bfr[ni][0], bfr[ni][1]);
        }
        __syncthreads();   // all warps done with stage it%2 before it is refilled

        if (it + 2 < kIters) issue_stage(it + 2, (it + 2) % GSTAGES);
    }

    // Epilogue: rows (g, g+8), cols (2t, 2t+1) per fragment, plus bias
#pragma unroll
    for (int ni = 0; ni < 4; ni++) {
        const int cc = bn + wn + ni * 8 + 2 * t;
        float2 bv = make_float2(0.f, 0.f);
        if (bias) bv = *(const float2*)(bias + cc);
#pragma unroll
        for (int mi = 0; mi < 4; mi++) {
            const int rr = bm + wm + mi * 16 + g;
            *(float2*)(C + (size_t)rr * N + cc) =
                make_float2(acc[mi][ni][0] + bv.x, acc[mi][ni][1] + bv.y);
            *(float2*)(C + (size_t)(rr + 8) * N + cc) =
                make_float2(acc[mi][ni][2] + bv.x, acc[mi][ni][3] + bv.y);
        }
    }
}

// ---------------------------------------------------------------------------
// RoPE + tf32 conditioning of q (ATT_SCALE folded), k, v.
// ---------------------------------------------------------------------------
__global__ void rope_kernel(const float* __restrict__ fc, const float* __restrict__ fs)
{
    const int NQ = MROWS * HH * 64;
    const int NK = MROWS * KVH * 64;
    int idx = blockIdx.x * 256 + threadIdx.x;
    if (idx < NQ) {
        int d = idx & 63;
        int h = (idx >> 6) % HH;
        int row = idx / (64 * HH);
        int s = row & (SS - 1);
        float c = fc[s * 64 + d], sn = fs[s * 64 + d];
        float* p = g_q + (size_t)row * QN + h * HDIM + 2 * d;
        float xr = p[0], xi = p[1];
        p[0] = tf32r(ATT_SCALE * (xr * c - xi * sn));
        p[1] = tf32r(ATT_SCALE * (xr * sn + xi * c));
    } else if (idx < NQ + NK) {
        int j = idx - NQ;
        int d = j & 63;
        int h = (j >> 6) & 3;
        int row = j >> 8;
        int s = row & (SS - 1);
        float c = fc[s * 64 + d], sn = fs[s * 64 + d];
        float* p = g_k + (size_t)row * KN + h * HDIM + 2 * d;
        float xr = p[0], xi = p[1];
        p[0] = tf32r(xr * c - xi * sn);
        p[1] = tf32r(xr * sn + xi * c);
    } else {
        int j = idx - NQ - NK;
        int d = j & 63;
        int h = (j >> 6) & 3;
        int row = j >> 8;
        float* p = g_v + (size_t)row * KN + h * HDIM + 2 * d;
        p[0] = tf32r(p[0]);
        p[1] = tf32r(p[1]);
    }
}

// ---------------------------------------------------------------------------
// Flash attention on tf32 tensor cores (passing R7/R9 design; finalize writes
// tf32-clean values so the O-projection GEMM needs no conversion).
// ---------------------------------------------------------------------------
#define KS_W 132
#define VS_W 136
#define PS_W 76
#define FLASH_SMEM_WORDS (64*KS_W + 64*VS_W + 128*PS_W)   // 26880 words

__global__ __launch_bounds__(256) void flash_tc()
{
    extern __shared__ uint32_t smf[];
    uint32_t* Ks = smf;
    uint32_t* Vs = smf + 64 * KS_W;
    uint32_t* Ps = smf + 64 * KS_W + 64 * VS_W;

    const int m0 = (gridDim.x - 1 - blockIdx.x) * 128;
    const int h = blockIdx.y;
    const int b = blockIdx.z;
    const int kvh = h / NREP;
    const int tid = threadIdx.x;
    const int W = tid >> 5;
    const int lane = tid & 31;
    const int g = lane >> 2;
    const int t = lane & 3;

    const float* qb = g_q + (size_t)(b * SS + m0 + W * 16) * QN + h * HDIM;
    uint32_t qf[16][4];
#pragma unroll
    for (int ks = 0; ks < 16; ks++) {
        qf[ks][0] = __float_as_uint(qb[(size_t)g * QN + ks * 8 + t]);
        qf[ks][1] = __float_as_uint(qb[(size_t)(g + 8) * QN + ks * 8 + t]);
        qf[ks][2] = __float_as_uint(qb[(size_t)g * QN + ks * 8 + t + 4]);
        qf[ks][3] = __float_as_uint(qb[(size_t)(g + 8) * QN + ks * 8 + t + 4]);
    }

    float accO[16][4];
#pragma unroll
    for (int nf = 0; nf < 16; nf++)
#pragma unroll
        for (int e = 0; e < 4; e++) accO[nf][e] = 0.f;
    float mrow[2] = {-1e30f, -1e30f};
    float lrow[2] = {0.f, 0.f};

    const int prow0 = (W * 16 + g) * PS_W;

    const int jcount = m0 / 64 + 2;
    for (int jt = 0; jt < jcount; jt++) {
        const int t0 = jt * 64;
        __syncthreads();

        const float* kb = g_k + (size_t)(b * SS + t0) * KN + kvh * HDIM;
        const float* vb = g_v + (size_t)(b * SS + t0) * KN + kvh * HDIM;
#pragma unroll
        for (int it = 0; it < 8; it++) {
            const int e = it * 256 + tid;
            const int r = e >> 5;
            const int d4 = (e & 31) << 2;
            *(uint4*)&Ks[r * KS_W + d4] = *(const uint4*)(kb + (size_t)r * KN + d4);
            *(uint4*)&Vs[r * VS_W + d4] = *(const uint4*)(vb + (size_t)r * KN + d4);
        }
        __syncthreads();

        float sacc[8][4];
#pragma unroll
        for (int nf = 0; nf < 8; nf++)
#pragma unroll
            for (int e = 0; e < 4; e++) sacc[nf][e] = 0.f;

#pragma unroll
        for (int ks = 0; ks < 16; ks++) {
#pragma unroll
            for (int nf = 0; nf < 8; nf++) {
                const uint32_t b0 = Ks[(nf * 8 + g) * KS_W + ks * 8 + t];
                const uint32_t b1 = Ks[(nf * 8 + g) * KS_W + ks * 8 + t + 4];
                mma_tf32(sacc[nf], qf[ks][0], qf[ks][1], qf[ks][2], qf[ks][3], b0, b1);
            }
        }

        if (jt >= jcount - 2) {
            const int r0 = m0 + W * 16 + g;
            const int r1 = r0 + 8;
#pragma unroll
            for (int nf = 0; nf < 8; nf++) {
                const int c0 = t0 + nf * 8 + 2 * t;
                if (c0 > r0)     sacc[nf][0] = -1e30f;
                if (c0 + 1 > r0) sacc[nf][1] = -1e30f;
                if (c0 > r1)     sacc[nf][2] = -1e30f;
                if (c0 + 1 > r1) sacc[nf][3] = -1e30f;
            }
        }

        float alpha[2];
#pragma unroll
        for (int i = 0; i < 2; i++) {
            float rm = -1e30f;
#pragma unroll
            for (int nf = 0; nf < 8; nf++)
                rm = fmaxf(rm, fmaxf(sacc[nf][2 * i], sacc[nf][2 * i + 1]));
            rm = fmaxf(rm, __shfl_xor_sync(0xffffffffu, rm, 1));
            rm = fmaxf(rm, __shfl_xor_sync(0xffffffffu, rm, 2));
            const float mn = fmaxf(mrow[i], rm);
            alpha[i] = __expf(mrow[i] - mn);
            float rs = 0.f;
#pragma unroll
            for (int nf = 0; nf < 8; nf++) {
                const float e0 = __expf(sacc[nf][2 * i] - mn);
                const float e1 = __expf(sacc[nf][2 * i + 1] - mn);
                sacc[nf][2 * i] = e0;
                sacc[nf][2 * i + 1] = e1;
                rs += e0 + e1;
            }
            rs += __shfl_xor_sync(0xffffffffu, rs, 1);
            rs += __shfl_xor_sync(0xffffffffu, rs, 2);
            lrow[i] = lrow[i] * alpha[i] + rs;
            mrow[i] = mn;
        }
#pragma unroll
        for (int nf = 0; nf < 16; nf++) {
            accO[nf][0] *= alpha[0]; accO[nf][1] *= alpha[0];
            accO[nf][2] *= alpha[1]; accO[nf][3] *= alpha[1];
        }

#pragma unroll
        for (int nf = 0; nf < 8; nf++) {
            const int c = nf * 8 + 2 * t;
            Ps[prow0 + c]                = f2tf32(sacc[nf][0]);
            Ps[prow0 + c + 1]            = f2tf32(sacc[nf][1]);
            Ps[prow0 + 8 * PS_W + c]     = f2tf32(sacc[nf][2]);
            Ps[prow0 + 8 * PS_W + c + 1] = f2tf32(sacc[nf][3]);
        }
        __syncwarp();

#pragma unroll
        for (int ks = 0; ks < 8; ks++) {
            const uint32_t a0 = Ps[prow0 + ks * 8 + t];
            const uint32_t a1 = Ps[prow0 + 8 * PS_W + ks * 8 + t];
            const uint32_t a2 = Ps[prow0 + ks * 8 + t + 4];
            const uint32_t a3 = Ps[prow0 + 8 * PS_W + ks * 8 + t + 4];
#pragma unroll
            for (int nf = 0; nf < 16; nf++) {
                const uint32_t b0 = Vs[(ks * 8 + t) * VS_W + nf * 8 + g];
                const uint32_t b1 = Vs[(ks * 8 + t + 4) * VS_W + nf * 8 + g];
                mma_tf32(accO[nf], a0, a1, a2, a3, b0, b1);
            }
        }
        __syncwarp();
    }

    const float inv0 = 1.f / lrow[0];
    const float inv1 = 1.f / lrow[1];
    float* ob = g_o + (size_t)(b * SS + m0 + W * 16) * QN + h * HDIM;
#pragma unroll
    for (int nf = 0; nf < 16; nf++) {
        const int c = nf * 8 + 2 * t;
        *(float2*)(ob + (size_t)g * QN + c) =
            make_float2(tf32r(accO[nf][0] * inv0), tf32r(accO[nf][1] * inv0));
        *(float2*)(ob + (size_t)(g + 8) * QN + c) =
            make_float2(tf32r(accO[nf][2] * inv1), tf32r(accO[nf][3] * inv1));
    }
}

// ---------------------------------------------------------------------------
// kernel_launch
// ---------------------------------------------------------------------------
extern "C" void kernel_launch(void* const* d_in, const int* in_sizes, int n_in,
                              void* d_out, int out_size)
{
    const float* x    = (const float*)d_in[0];
    const float* wq_w = (const float*)d_in[1];
    const float* wq_b = (const float*)d_in[2];
    const float* wk_w = (const float*)d_in[3];
    const float* wk_b = (const float*)d_in[4];
    const float* wv_w = (const float*)d_in[5];
    const float* wv_b = (const float*)d_in[6];
    const float* wo_w = (const float*)d_in[7];
    const float* fc   = (const float*)d_in[10];
    const float* fs   = (const float*)d_in[11];
    float* out = (float*)d_out;

    const int flash_smem = FLASH_SMEM_WORDS * 4;   // 107,520 B
    cudaFuncSetAttribute(flash_tc, cudaFuncAttributeMaxDynamicSharedMemorySize, flash_smem);
    cudaFuncSetAttribute(gemm_pipe, cudaFuncAttributeMaxDynamicSharedMemorySize, GEMM_SMEM_BYTES);

    // tf32-condition all GEMM operands once
    convert_tf32<<<CVT_BLOCKS, 256>>>(x, wq_w, wk_w, wv_w, wo_w);

    // QKV projections (pipelined tf32 tensor-core GEMM, 2 CTAs/SM)
    gemm_pipe<<<dim3(QN / 128, MROWS / 128), 256, GEMM_SMEM_BYTES>>>(
        SRC_XA, SRC_WQ, wq_b, nullptr, DST_Q, MROWS, QN, DD);
    gemm_pipe<<<dim3(KN / 128, MROWS / 128), 256, GEMM_SMEM_BYTES>>>(
        SRC_XA, SRC_WK, wk_b, nullptr, DST_K, MROWS, KN, DD);
    gemm_pipe<<<dim3(KN / 128, MROWS / 128), 256, GEMM_SMEM_BYTES>>>(
        SRC_XA, SRC_WV, wv_b, nullptr, DST_V, MROWS, KN, DD);

    // RoPE + tf32 conditioning of q (scaled), k, v
    rope_kernel<<<(MROWS * HH * 64 + 2 * MROWS * KVH * 64) / 256, 256>>>(fc, fs);

    // Causal GQA flash attention on tensor cores: g_q,g_k,g_v -> g_o
    flash_tc<<<dim3(SS / 128, HH, BB), 256, flash_smem>>>();

    // Output projection: g_o @ wo_w^T -> out
    gemm_pipe<<<dim3(QN / 128, MROWS / 128), 256, GEMM_SMEM_BYTES>>>(
        SRC_O, SRC_WO, nullptr, out, DST_EXT, MROWS, QN, DD);
}